// round 4
// baseline (speedup 1.0000x reference)
#include <cuda_runtime.h>
#include <cstdint>

#define Bn 64
#define Tn 1024
#define HROWS 512               // rows per CTA (half batch)
#define NTh 256
#define NWARP 8
#define NLOC (Tn + 31)          // 1055 local iterations per warp
#define FINF 1000000000.0f
#define ALPHA 0.7f
#define GLN2 0.13862943611198906f      // gamma*ln2
#define SSCALE 2.6857913f              // sqrt(1/(gamma*ln2))

__device__ float g_mse[Bn * 2 * NWARP];     // 1024 partials
__device__ float g_r[Bn];
__device__ float g_edge[Bn][Tn];            // row-511 R' values, per batch
__device__ int   g_prog[Bn];                // edge columns published

__device__ __forceinline__ float ex2f(float x) {
    float y; asm("ex2.approx.ftz.f32 %0, %1;" : "=f"(y) : "f"(x)); return y;
}
__device__ __forceinline__ float lg2f(float x) {
    float y; asm("lg2.approx.ftz.f32 %0, %1;" : "=f"(y) : "f"(x)); return y;
}
__device__ __forceinline__ int ld_acq(const int* p) {
    int v; uint32_t a = (uint32_t)__cvta_generic_to_shared(p);
    asm volatile("ld.acquire.cta.shared.b32 %0, [%1];" : "=r"(v) : "r"(a));
    return v;
}
__device__ __forceinline__ void st_rel(int* p, int v) {
    uint32_t a = (uint32_t)__cvta_generic_to_shared(p);
    asm volatile("st.release.cta.shared.b32 [%0], %1;" :: "r"(a), "r"(v));
}
__device__ __forceinline__ int ld_acq_gpu(const int* p) {
    int v; asm volatile("ld.acquire.gpu.global.b32 %0, [%1];" : "=r"(v) : "l"(p));
    return v;
}
__device__ __forceinline__ void st_rel_gpu(int* p, int v) {
    asm volatile("st.release.gpu.global.b32 [%0], %1;" :: "l"(p), "r"(v));
}
__device__ __forceinline__ float ldcg(const float* p) {
    float v; asm volatile("ld.global.cg.f32 %0, [%1];" : "=f"(v) : "l"(p));
    return v;
}

__global__ void init_kernel() {
    if (threadIdx.x < Bn) g_prog[threadIdx.x] = 0;
}

__global__ __launch_bounds__(NTh, 1)
void sdtw_kernel(const float* __restrict__ pred, const float* __restrict__ target)
{
    __shared__ float4 tgA[Tn];             // -2*SSCALE*target[0..3]
    __shared__ float4 tgB[Tn];             // -2*SSCALE*target[4..7]
    __shared__ float  y2s[Tn];             // SSCALE^2 * |target|^2
    __shared__ float  edge[NWARP + 1][64]; // [w]: warp w ring; [8]: virtual producer ring
    __shared__ int    prog[NWARP];

    const int  b    = blockIdx.x >> 1;
    const bool isHi = blockIdx.x & 1;
    const int  t    = threadIdx.x;
    const int  lane = t & 31;
    const int  w    = t >> 5;

    // ---- preprocessing ----
    // target: ALL 1024 rows, 4 per thread
    for (int k = 0; k < 4; ++k) {
        const int r = 4 * t + k;
        const float* trow = target + ((size_t)b * Tn + r) * 8;
        float y2 = 0.f, ts[8];
#pragma unroll
        for (int c = 0; c < 8; ++c) {
            float u = trow[c] * SSCALE;
            ts[c] = -2.f * u;
            y2 = fmaf(u, u, y2);
        }
        tgA[r] = make_float4(ts[0], ts[1], ts[2], ts[3]);
        tgB[r] = make_float4(ts[4], ts[5], ts[6], ts[7]);
        y2s[r] = y2;
    }
    // pred: this CTA's 512 rows, 2 per thread; MSE over this half
    const int rbase = (isHi ? HROWS : 0) + 2 * t;
    const float* prow = pred   + ((size_t)b * Tn + rbase) * 8;
    const float* urow = target + ((size_t)b * Tn + rbase) * 8;
    float P0[8], P1[8];
    float x20 = 0.f, x21 = 0.f, msep = 0.f;
#pragma unroll
    for (int c = 0; c < 8; ++c) {
        float p0 = prow[c], p1 = prow[8 + c];
        float u0 = urow[c], u1 = urow[8 + c];
        float d0 = p0 - u0, d1 = p1 - u1;
        msep = fmaf(d0, d0, msep); msep = fmaf(d1, d1, msep);
        P0[c] = p0 * SSCALE; P1[c] = p1 * SSCALE;
        x20 = fmaf(P0[c], P0[c], x20);
        x21 = fmaf(P1[c], P1[c], x21);
    }
#pragma unroll
    for (int off = 16; off > 0; off >>= 1)
        msep += __shfl_xor_sync(0xffffffffu, msep, off);
    if (lane == 0) g_mse[(b * 2 + (isHi ? 1 : 0)) * NWARP + w] = msep;

    if (t < 64) edge[NWARP][t] = FINF;     // virtual ring default (lo w0 reads FINF)
    if (t < NWARP) prog[t] = 0;
    __syncthreads();                        // the only block barrier

    // ---- warp-systolic wavefront ----
    float r0 = FINF, r1 = FINF;
    float nbrA = (!isHi && w == 0 && lane == 0) ? 0.0f : FINF;  // (0,0) diag seed
    float nbrB = FINF;

    const float* prodRing = (w > 0) ? edge[w - 1] : edge[NWARP];
    float*       edgeW    = edge[w];
    float*       vring    = edge[NWARP];
    const bool hasProd = (w > 0);
    const bool hasCons = (w < NWARP - 1);
    const bool gprod   = (!isHi && w == NWARP - 1);   // feeds hi CTA via gmem
    const bool gcons   = (isHi && w == 0);            // consumes gmem edge
    float* gedge = g_edge[b];
    int*   gpp   = &g_prog[b];

#define DTW_ITER(N)                                                            \
  {                                                                            \
    float sh = __shfl_up_sync(0xffffffffu, r1, 1);                             \
    float newA = (lane == 0) ? prodRing[((N) + 31) & 63] : sh;                 \
    nbrB = nbrA; nbrA = newA;                                                  \
    int j = (N) - lane;                                                        \
    bool valid = ((unsigned)j < (unsigned)Tn);                                 \
    int jc = valid ? j : 0;                                                    \
    float4 ga = tgA[jc]; float4 gb = tgB[jc]; float y2j = y2s[jc];             \
    float D0 = x20 + y2j, D1 = x21 + y2j;                                      \
    D0 = fmaf(P0[0], ga.x, D0); D0 = fmaf(P0[1], ga.y, D0);                    \
    D0 = fmaf(P0[2], ga.z, D0); D0 = fmaf(P0[3], ga.w, D0);                    \
    D0 = fmaf(P0[4], gb.x, D0); D0 = fmaf(P0[5], gb.y, D0);                    \
    D0 = fmaf(P0[6], gb.z, D0); D0 = fmaf(P0[7], gb.w, D0);                    \
    D1 = fmaf(P1[0], ga.x, D1); D1 = fmaf(P1[1], ga.y, D1);                    \
    D1 = fmaf(P1[2], ga.z, D1); D1 = fmaf(P1[3], ga.w, D1);                    \
    D1 = fmaf(P1[4], gb.x, D1); D1 = fmaf(P1[5], gb.y, D1);                    \
    D1 = fmaf(P1[6], gb.z, D1); D1 = fmaf(P1[7], gb.w, D1);                    \
    float mn  = fminf(nbrA, r0), mx  = fmaxf(nbrA, r0);                        \
    float v0  = fminf(mn, nbrB), md  = fmaxf(mn, nbrB);                        \
    float s0  = 1.0f + ex2f(v0 - md) + ex2f(v0 - mx);                          \
    float r0n = (D0 + v0) - lg2f(s0);                                          \
    r0n = valid ? r0n : FINF;                                                  \
    float mn1 = fminf(r0n, r1), mx1 = fmaxf(r0n, r1);                          \
    float v1  = fminf(mn1, r0), md1 = fmaxf(mn1, r0);                          \
    float s1  = 1.0f + ex2f(v1 - md1) + ex2f(v1 - mx1);                        \
    float r1n = (D1 + v1) - lg2f(s1);                                          \
    r1n = valid ? r1n : FINF;                                                  \
    r0 = r0n; r1 = r1n;                                                        \
    if (lane == 31) edgeW[(N) & 63] = r1n;                                     \
    if (gprod && lane == 31 && (N) >= 31) gedge[(N) - 31] = r1n;               \
  }

    float regv = 0.f;   // gcons prefetch register (lanes 0..7)
    if (gcons) {
        // prologue: cols 0..7 -> ring; cols 8..15 -> regv
        while (ld_acq_gpu(gpp) < 16) __nanosleep(64);
        if (lane < 8) vring[(lane + 31) & 63] = ldcg(&gedge[lane]);
        if (lane < 8) regv = ldcg(&gedge[8 + lane]);
        __syncwarp();
    }

    int n = 0;
#pragma unroll 1
    for (int mb = 0; mb < 131; ++mb) {     // 131*8 = 1048 iters
        if (gcons) {
            int need = n + 24; if (need > 1024) need = 1024;
            while (ld_acq_gpu(gpp) < need) __nanosleep(64);
            if (lane < 8) {
                int col = n + 8 + lane;
                vring[(col + 31) & 63] = regv;
                int nc = n + 16 + lane; if (nc > Tn - 1) nc = Tn - 1;
                regv = ldcg(&gedge[nc]);
            }
            __syncwarp();
        } else if (hasProd) {
            int need = ((n + 7 < Tn - 1) ? (n + 7) : (Tn - 1)) + 32;
            while (ld_acq(&prog[w - 1]) < need) __nanosleep(32);
        }
        if (hasCons && n >= 87) {
            int lim = n - 86;
            while (ld_acq(&prog[w + 1]) < lim) __nanosleep(32);
        }
        DTW_ITER(n)     DTW_ITER(n + 1) DTW_ITER(n + 2) DTW_ITER(n + 3)
        DTW_ITER(n + 4) DTW_ITER(n + 5) DTW_ITER(n + 6) DTW_ITER(n + 7)
        n += 8;
        st_rel(&prog[w], n);
        if (gprod && lane == 31 && n >= 32) st_rel_gpu(gpp, n - 31);
    }
    // tail: n = 1048..1054 (7 iters)
    {
        if (!gcons && hasProd) {
            while (ld_acq(&prog[w - 1]) < NLOC) __nanosleep(32);
        }
        DTW_ITER(n)     DTW_ITER(n + 1) DTW_ITER(n + 2) DTW_ITER(n + 3)
        DTW_ITER(n + 4) DTW_ITER(n + 5) DTW_ITER(n + 6)
        st_rel(&prog[w], NLOC);
        if (gprod && lane == 31) st_rel_gpu(gpp, Tn);
    }
#undef DTW_ITER

    if (isHi && w == NWARP - 1 && lane == 31) g_r[b] = r1;   // R'[T-1][T-1]
}

__global__ void finalize_kernel(float* out)
{
    __shared__ float sm[256];
    const int t = threadIdx.x;

    float a = 0.f;
    for (int i = t; i < Bn * 2 * NWARP; i += 256) a += g_mse[i];
    sm[t] = a;
    __syncthreads();
#pragma unroll
    for (int s = 128; s > 0; s >>= 1) {
        if (t < s) sm[t] += sm[t + s];
        __syncthreads();
    }
    const float mse_sum = sm[0];
    __syncthreads();

    float r = 0.f;
    for (int i = t; i < Bn; i += 256) r += g_r[i];
    sm[t] = r;
    __syncthreads();
#pragma unroll
    for (int s = 128; s > 0; s >>= 1) {
        if (t < s) sm[t] += sm[t + s];
        __syncthreads();
    }
    if (t == 0) {
        const float mse  = mse_sum / (float)(Bn * Tn * 8);
        const float sdtw = (GLN2 * sm[0]) / (float)Bn;
        out[0] = ALPHA * mse + (1.0f - ALPHA) * sdtw;
    }
}

extern "C" void kernel_launch(void* const* d_in, const int* in_sizes, int n_in,
                              void* d_out, int out_size)
{
    (void)in_sizes; (void)n_in; (void)out_size;
    const float* pred   = (const float*)d_in[0];
    const float* target = (const float*)d_in[1];
    float* out = (float*)d_out;

    init_kernel<<<1, 64>>>();
    sdtw_kernel<<<2 * Bn, NTh>>>(pred, target);
    finalize_kernel<<<1, 256>>>(out);
}

// round 6
// speedup vs baseline: 1.2499x; 1.2499x over previous
#include <cuda_runtime.h>
#include <cstdint>

#define Bn 64
#define Tn 1024
#define HROWS 512               // rows per CTA (half batch)
#define NTh 256
#define NWARP 8
#define NLOC (Tn + 31)          // 1055 local iterations per warp
#define FINF 1000000000.0f
#define ALPHA 0.7f
#define GLN2 0.13862943611198906f      // gamma*ln2
#define SSCALE 2.6857913f              // sqrt(1/(gamma*ln2))
#define SENT 0x7FC00BADu               // NaN bit pattern; recursion never produces NaN

__device__ float g_mse[Bn * 2 * NWARP];
__device__ float g_r[Bn];
__device__ float g_edge[Bn][Tn];            // row-511 R' values, per batch

__device__ __forceinline__ float ex2f(float x) {
    float y; asm("ex2.approx.ftz.f32 %0, %1;" : "=f"(y) : "f"(x)); return y;
}
__device__ __forceinline__ float lg2f(float x) {
    float y; asm("lg2.approx.ftz.f32 %0, %1;" : "=f"(y) : "f"(x)); return y;
}
__device__ __forceinline__ int ld_acq(const int* p) {
    int v; uint32_t a = (uint32_t)__cvta_generic_to_shared(p);
    asm volatile("ld.acquire.cta.shared.b32 %0, [%1];" : "=r"(v) : "r"(a));
    return v;
}
__device__ __forceinline__ void st_rel(int* p, int v) {
    uint32_t a = (uint32_t)__cvta_generic_to_shared(p);
    asm volatile("st.release.cta.shared.b32 [%0], %1;" :: "r"(a), "r"(v));
}
__device__ __forceinline__ float ldcg(const float* p) {
    float v; asm volatile("ld.global.cg.f32 %0, [%1];" : "=f"(v) : "l"(p));
    return v;
}
__device__ __forceinline__ void stcg(float* p, float v) {
    asm volatile("st.global.cg.f32 [%0], %1;" :: "l"(p), "f"(v));
}

// Re-sentinel the edge array every launch (runs inside the graph, same stream).
__global__ void init_kernel() {
    const int i = blockIdx.x * 1024 + threadIdx.x * 4;
    float* p = &g_edge[0][0];
    const float s = __uint_as_float(SENT);
    p[i] = s; p[i + 1] = s; p[i + 2] = s; p[i + 3] = s;
}

__global__ __launch_bounds__(NTh, 1)
void sdtw_kernel(const float* __restrict__ pred, const float* __restrict__ target)
{
    __shared__ float4 tgA[Tn];             // -2*SSCALE*target[0..3]
    __shared__ float4 tgB[Tn];             // -2*SSCALE*target[4..7]
    __shared__ float  y2s[Tn];             // SSCALE^2 * |target|^2
    __shared__ float  edge[NWARP + 1][64]; // [w]: warp w ring; [8]: virtual producer ring
    __shared__ int    prog[NWARP];

    const int  b    = blockIdx.x >> 1;
    const bool isHi = blockIdx.x & 1;
    const int  t    = threadIdx.x;
    const int  lane = t & 31;
    const int  w    = t >> 5;

    // ---- preprocessing ----
    for (int k = 0; k < 4; ++k) {
        const int r = 4 * t + k;
        const float* trow = target + ((size_t)b * Tn + r) * 8;
        float y2 = 0.f, ts[8];
#pragma unroll
        for (int c = 0; c < 8; ++c) {
            float u = trow[c] * SSCALE;
            ts[c] = -2.f * u;
            y2 = fmaf(u, u, y2);
        }
        tgA[r] = make_float4(ts[0], ts[1], ts[2], ts[3]);
        tgB[r] = make_float4(ts[4], ts[5], ts[6], ts[7]);
        y2s[r] = y2;
    }
    const int rbase = (isHi ? HROWS : 0) + 2 * t;
    const float* prow = pred   + ((size_t)b * Tn + rbase) * 8;
    const float* urow = target + ((size_t)b * Tn + rbase) * 8;
    float P0[8], P1[8];
    float x20 = 0.f, x21 = 0.f, msep = 0.f;
#pragma unroll
    for (int c = 0; c < 8; ++c) {
        float p0 = prow[c], p1 = prow[8 + c];
        float u0 = urow[c], u1 = urow[8 + c];
        float d0 = p0 - u0, d1 = p1 - u1;
        msep = fmaf(d0, d0, msep); msep = fmaf(d1, d1, msep);
        P0[c] = p0 * SSCALE; P1[c] = p1 * SSCALE;
        x20 = fmaf(P0[c], P0[c], x20);
        x21 = fmaf(P1[c], P1[c], x21);
    }
#pragma unroll
    for (int off = 16; off > 0; off >>= 1)
        msep += __shfl_xor_sync(0xffffffffu, msep, off);
    if (lane == 0) g_mse[(b * 2 + (isHi ? 1 : 0)) * NWARP + w] = msep;

    if (t < 64) edge[NWARP][t] = FINF;     // virtual ring default (lo w0 reads FINF)
    if (t < NWARP) prog[t] = 0;
    __syncthreads();                        // the only block barrier

    // ---- warp-systolic wavefront ----
    float r0 = FINF, r1 = FINF;
    float nbrA = (!isHi && w == 0 && lane == 0) ? 0.0f : FINF;  // (0,0) diag seed
    float nbrB = FINF;

    const float* prodRing = (w > 0) ? edge[w - 1] : edge[NWARP];
    float*       edgeW    = edge[w];
    float*       vring    = edge[NWARP];
    const bool hasProd = (w > 0);
    const bool hasCons = (w < NWARP - 1);
    const bool gprod   = (!isHi && w == NWARP - 1);   // feeds hi CTA via gmem
    const bool gcons   = (isHi && w == 0);            // consumes gmem edge
    float* gedge = g_edge[b];

#define DTW_ITER(N)                                                            \
  {                                                                            \
    float sh = __shfl_up_sync(0xffffffffu, r1, 1);                             \
    float newA = (lane == 0) ? prodRing[((N) + 31) & 63] : sh;                 \
    nbrB = nbrA; nbrA = newA;                                                  \
    int j = (N) - lane;                                                        \
    bool valid = ((unsigned)j < (unsigned)Tn);                                 \
    int jc = valid ? j : 0;                                                    \
    float4 ga = tgA[jc]; float4 gb = tgB[jc]; float y2j = y2s[jc];             \
    float D0 = x20 + y2j, D1 = x21 + y2j;                                      \
    D0 = fmaf(P0[0], ga.x, D0); D0 = fmaf(P0[1], ga.y, D0);                    \
    D0 = fmaf(P0[2], ga.z, D0); D0 = fmaf(P0[3], ga.w, D0);                    \
    D0 = fmaf(P0[4], gb.x, D0); D0 = fmaf(P0[5], gb.y, D0);                    \
    D0 = fmaf(P0[6], gb.z, D0); D0 = fmaf(P0[7], gb.w, D0);                    \
    D1 = fmaf(P1[0], ga.x, D1); D1 = fmaf(P1[1], ga.y, D1);                    \
    D1 = fmaf(P1[2], ga.z, D1); D1 = fmaf(P1[3], ga.w, D1);                    \
    D1 = fmaf(P1[4], gb.x, D1); D1 = fmaf(P1[5], gb.y, D1);                    \
    D1 = fmaf(P1[6], gb.z, D1); D1 = fmaf(P1[7], gb.w, D1);                    \
    float mn  = fminf(nbrA, r0), mx  = fmaxf(nbrA, r0);                        \
    float v0  = fminf(mn, nbrB), md  = fmaxf(mn, nbrB);                        \
    float s0  = 1.0f + ex2f(v0 - md) + ex2f(v0 - mx);                          \
    float r0n = (D0 + v0) - lg2f(s0);                                          \
    r0n = valid ? r0n : FINF;                                                  \
    float mn1 = fminf(r0n, r1), mx1 = fmaxf(r0n, r1);                          \
    float v1  = fminf(mn1, r0), md1 = fmaxf(mn1, r0);                          \
    float s1  = 1.0f + ex2f(v1 - md1) + ex2f(v1 - mx1);                        \
    float r1n = (D1 + v1) - lg2f(s1);                                          \
    r1n = valid ? r1n : FINF;                                                  \
    r0 = r0n; r1 = r1n;                                                        \
    if (lane == 31) edgeW[(N) & 63] = r1n;                                     \
    if (gprod && lane == 31 && (N) >= 31) stcg(&gedge[(N) - 31], r1n);         \
  }

    float regv = 0.f;   // gcons prefetch register (lanes 0..7)
    if (gcons) {
        if (lane < 8) {
            float v = ldcg(&gedge[lane]);           // cols 0..7
            while (__float_as_int(v) == (int)SENT) { __nanosleep(64); v = ldcg(&gedge[lane]); }
            vring[(lane + 31) & 63] = v;
            regv = ldcg(&gedge[8 + lane]);          // cols 8..15 (checked at insertion)
        }
        __syncwarp();
    }

    int n = 0;
#pragma unroll 1
    for (int mb = 0; mb < 131; ++mb) {     // 131*8 = 1048 iters
        if (gcons) {
            if (lane < 8) {
                int col = n + 8 + lane;                       // insert col (<= 1055)
                int cc  = col < Tn - 1 ? col : Tn - 1;        // clamped load index
                while (__float_as_int(regv) == (int)SENT) {   // rare: producer behind
                    __nanosleep(40); regv = ldcg(&gedge[cc]);
                }
                vring[(col + 31) & 63] = regv;
                int nc = n + 16 + lane; if (nc > Tn - 1) nc = Tn - 1;
                regv = ldcg(&gedge[nc]);                      // prefetch 16 ahead
            }
            __syncwarp();
        } else if (hasProd) {
            int need = ((n + 7 < Tn - 1) ? (n + 7) : (Tn - 1)) + 32;
            while (ld_acq(&prog[w - 1]) < need) __nanosleep(32);
        }
        if (hasCons && n >= 87) {
            int lim = n - 86;
            while (ld_acq(&prog[w + 1]) < lim) __nanosleep(32);
        }
        DTW_ITER(n)     DTW_ITER(n + 1) DTW_ITER(n + 2) DTW_ITER(n + 3)
        DTW_ITER(n + 4) DTW_ITER(n + 5) DTW_ITER(n + 6) DTW_ITER(n + 7)
        n += 8;
        st_rel(&prog[w], n);
    }
    // tail: n = 1048..1054 (7 iters)
    {
        if (!gcons && hasProd) {
            while (ld_acq(&prog[w - 1]) < NLOC) __nanosleep(32);
        }
        DTW_ITER(n)     DTW_ITER(n + 1) DTW_ITER(n + 2) DTW_ITER(n + 3)
        DTW_ITER(n + 4) DTW_ITER(n + 5) DTW_ITER(n + 6)
        st_rel(&prog[w], NLOC);
    }
#undef DTW_ITER

    if (isHi && w == NWARP - 1 && lane == 31) g_r[b] = r1;   // R'[T-1][T-1]
}

__global__ void finalize_kernel(float* out)
{
    __shared__ float sm[256];
    const int t = threadIdx.x;

    float a = 0.f;
    for (int i = t; i < Bn * 2 * NWARP; i += 256) a += g_mse[i];
    sm[t] = a;
    __syncthreads();
#pragma unroll
    for (int s = 128; s > 0; s >>= 1) {
        if (t < s) sm[t] += sm[t + s];
        __syncthreads();
    }
    const float mse_sum = sm[0];
    __syncthreads();

    float r = 0.f;
    for (int i = t; i < Bn; i += 256) r += g_r[i];
    sm[t] = r;
    __syncthreads();
#pragma unroll
    for (int s = 128; s > 0; s >>= 1) {
        if (t < s) sm[t] += sm[t + s];
        __syncthreads();
    }
    if (t == 0) {
        const float mse  = mse_sum / (float)(Bn * Tn * 8);
        const float sdtw = (GLN2 * sm[0]) / (float)Bn;
        out[0] = ALPHA * mse + (1.0f - ALPHA) * sdtw;
    }
}

extern "C" void kernel_launch(void* const* d_in, const int* in_sizes, int n_in,
                              void* d_out, int out_size)
{
    (void)in_sizes; (void)n_in; (void)out_size;
    const float* pred   = (const float*)d_in[0];
    const float* target = (const float*)d_in[1];
    float* out = (float*)d_out;

    init_kernel<<<Bn, 256>>>();
    sdtw_kernel<<<2 * Bn, NTh>>>(pred, target);
    finalize_kernel<<<1, 256>>>(out);
}